// round 1
// baseline (speedup 1.0000x reference)
#include <cuda_runtime.h>

#define LQ  2048
#define SK  2048
#define NB  4
#define EMB 512
#define NH  16
#define HD  32
#define ROWS (LQ * NB)   // 8192

// Scratch (allocation-free rule: __device__ globals)
__device__ float g_Q[NB * NH * LQ * HD];   // [n,h,l,d] fp32, beta applied at attn load
__device__ float g_K[NB * NH * SK * HD];   // [n,h,s,d]
__device__ float g_V[NB * NH * SK * HD];
__device__ float g_O[ROWS * EMB];          // attention output, (l*NB+n, e) row-major

// ---------------------------------------------------------------------------
// Tiled fp32 GEMM: out[r,f] = sum_e A[r,e] * W[f,e] + bias[f]
// BM=128, BN=64, BK=16, 256 threads, 8x4 microtile.
// MODE 0: QKV projection (z picks input/weight-slice/dest scratch, epilogue
//         scatters into [n,h,len,d] layout)
// MODE 1: out-projection (A = g_O, plain row-major output)
// ---------------------------------------------------------------------------
template<int MODE>
__global__ __launch_bounds__(256)
void gemm_kernel(const float* __restrict__ Aq, const float* __restrict__ Ak,
                 const float* __restrict__ Av, const float* __restrict__ Wfull,
                 const float* __restrict__ bfull, float* __restrict__ outp)
{
    __shared__ float As[16][132];  // [k][m], padded vs bank conflicts
    __shared__ float Bs[16][68];   // [k][n]

    const int tid = threadIdx.x;
    const int r0  = blockIdx.x * 128;
    const int f0  = blockIdx.y * 64;

    const float* A;
    const float* W;
    const float* bias;
    if (MODE == 0) {
        const int z = blockIdx.z;
        A    = (z == 0) ? Aq : (z == 1) ? Ak : Av;
        W    = Wfull + z * EMB * EMB;
        bias = bfull + z * EMB;
    } else {
        A    = g_O;
        W    = Wfull;
        bias = bfull;
    }

    const int ty = tid >> 4;   // 0..15 (row group of 8)
    const int tx = tid & 15;   // 0..15 (col group of 4)

    float acc[8][4];
    #pragma unroll
    for (int i = 0; i < 8; i++)
        #pragma unroll
        for (int j = 0; j < 4; j++) acc[i][j] = 0.f;

    for (int k0 = 0; k0 < EMB; k0 += 16) {
        // Load A tile: 128x16 = 512 float4 loads, 2 per thread
        #pragma unroll
        for (int t = tid; t < 512; t += 256) {
            const int row = t >> 2;
            const int kk  = (t & 3) << 2;
            const float4 v = *(const float4*)(A + (size_t)(r0 + row) * EMB + k0 + kk);
            As[kk + 0][row] = v.x;
            As[kk + 1][row] = v.y;
            As[kk + 2][row] = v.z;
            As[kk + 3][row] = v.w;
        }
        // Load B tile: 64x16 = 256 float4 loads, 1 per thread
        {
            const int n  = tid >> 2;
            const int kk = (tid & 3) << 2;
            const float4 v = *(const float4*)(W + (size_t)(f0 + n) * EMB + k0 + kk);
            Bs[kk + 0][n] = v.x;
            Bs[kk + 1][n] = v.y;
            Bs[kk + 2][n] = v.z;
            Bs[kk + 3][n] = v.w;
        }
        __syncthreads();

        #pragma unroll
        for (int k = 0; k < 16; k++) {
            float a[8], b[4];
            #pragma unroll
            for (int i = 0; i < 8; i++) a[i] = As[k][ty * 8 + i];
            #pragma unroll
            for (int j = 0; j < 4; j++) b[j] = Bs[k][tx * 4 + j];
            #pragma unroll
            for (int i = 0; i < 8; i++)
                #pragma unroll
                for (int j = 0; j < 4; j++) acc[i][j] += a[i] * b[j];
        }
        __syncthreads();
    }

    if (MODE == 0) {
        float* dst = (blockIdx.z == 0) ? g_Q : (blockIdx.z == 1) ? g_K : g_V;
        #pragma unroll
        for (int i = 0; i < 8; i++) {
            const int r = r0 + ty * 8 + i;
            const int l = r >> 2;      // / NB
            const int n = r & 3;       // % NB
            #pragma unroll
            for (int j = 0; j < 4; j++) {
                const int f = f0 + tx * 4 + j;
                const int h = f >> 5;
                const int d = f & 31;
                dst[((size_t)(n * NH + h) * LQ + l) * HD + d] = acc[i][j] + bias[f];
            }
        }
    } else {
        #pragma unroll
        for (int i = 0; i < 8; i++) {
            const int r = r0 + ty * 8 + i;
            #pragma unroll
            for (int j = 0; j < 4; j++) {
                const int f = f0 + tx * 4 + j;
                outp[(size_t)r * EMB + f] = acc[i][j] + bias[f];
            }
        }
    }
}

// ---------------------------------------------------------------------------
// LayerNorm over D=32 for K and V (one warp per row, shuffle reductions)
// ---------------------------------------------------------------------------
__global__ __launch_bounds__(256)
void ln_kernel(const float* __restrict__ w, const float* __restrict__ b)
{
    const int gw   = (blockIdx.x * blockDim.x + threadIdx.x) >> 5;
    const int lane = threadIdx.x & 31;
    const int R    = NB * NH * SK;
    if (gw >= 2 * R) return;
    float* X      = (gw < R) ? g_K : g_V;
    const int row = (gw < R) ? gw : gw - R;

    float x = X[(size_t)row * HD + lane];
    float s = x;
    #pragma unroll
    for (int o = 16; o; o >>= 1) s += __shfl_xor_sync(0xffffffffu, s, o);
    const float mu = s * (1.0f / HD);
    const float dv = x - mu;
    float vv = dv * dv;
    #pragma unroll
    for (int o = 16; o; o >>= 1) vv += __shfl_xor_sync(0xffffffffu, vv, o);
    const float inv = rsqrtf(vv * (1.0f / HD) + 1e-5f);
    X[(size_t)row * HD + lane] = dv * inv * w[lane] + b[lane];
}

// ---------------------------------------------------------------------------
// Flash attention: 1 thread = 1 query row, online softmax.
// Grid: (LQ/128, NB*NH), block 128. K/V tiles of 32 rows in smem (broadcast reads).
// ---------------------------------------------------------------------------
__global__ __launch_bounds__(128)
void attn_kernel(const float* __restrict__ scaling)
{
    __shared__ float Ks[32][HD];
    __shared__ float Vs[32][HD];

    const int tid  = threadIdx.x;
    const int nh   = blockIdx.y;             // n*NH + h
    const int h    = nh & (NH - 1);
    const int qrow = blockIdx.x * 128 + tid;
    const float beta = scaling[h];

    const float* Qp = g_Q + ((size_t)nh * LQ + qrow) * HD;
    float q[HD];
    #pragma unroll
    for (int d = 0; d < HD; d += 4) {
        const float4 v = *(const float4*)(Qp + d);
        q[d + 0] = v.x * beta;
        q[d + 1] = v.y * beta;
        q[d + 2] = v.z * beta;
        q[d + 3] = v.w * beta;
    }

    float m = -1e30f, lsum = 0.f;
    float acc[HD];
    #pragma unroll
    for (int d = 0; d < HD; d++) acc[d] = 0.f;

    const float* Kb = g_K + (size_t)nh * SK * HD;
    const float* Vb = g_V + (size_t)nh * SK * HD;

    for (int s0 = 0; s0 < SK; s0 += 32) {
        // cooperative tile load: 32x32 floats each = 256 float4, 2 per thread
        #pragma unroll
        for (int t = tid; t < 256; t += 128) {
            const int row = t >> 3;
            const int dd  = (t & 7) << 2;
            *(float4*)&Ks[row][dd] = *(const float4*)(Kb + (size_t)(s0 + row) * HD + dd);
            *(float4*)&Vs[row][dd] = *(const float4*)(Vb + (size_t)(s0 + row) * HD + dd);
        }
        __syncthreads();

        float sc[32];
        float tmax = -1e30f;
        #pragma unroll
        for (int j = 0; j < 32; j++) {
            float dot = 0.f;
            #pragma unroll
            for (int d = 0; d < HD; d++) dot += q[d] * Ks[j][d];
            sc[j] = dot;
            tmax = fmaxf(tmax, dot);
        }

        const float newm = fmaxf(m, tmax);
        const float corr = __expf(m - newm);
        lsum *= corr;
        #pragma unroll
        for (int d = 0; d < HD; d++) acc[d] *= corr;

        #pragma unroll
        for (int j = 0; j < 32; j++) {
            const float p = __expf(sc[j] - newm);
            lsum += p;
            #pragma unroll
            for (int d = 0; d < HD; d++) acc[d] += p * Vs[j][d];
        }
        m = newm;
        __syncthreads();
    }

    const float inv = 1.0f / lsum;
    const int l = qrow;
    const int n = nh >> 4;  // / NH
    float* op = g_O + ((size_t)l * NB + n) * EMB + h * HD;
    #pragma unroll
    for (int d = 0; d < HD; d++) op[d] = acc[d] * inv;
}

// ---------------------------------------------------------------------------
extern "C" void kernel_launch(void* const* d_in, const int* in_sizes, int n_in,
                              void* d_out, int out_size)
{
    const float* query   = (const float*)d_in[0];
    const float* key_in  = (const float*)d_in[1];
    const float* value   = (const float*)d_in[2];
    const float* scaling = (const float*)d_in[3];
    const float* in_w    = (const float*)d_in[4];
    const float* in_b    = (const float*)d_in[5];
    const float* pn_w    = (const float*)d_in[6];
    const float* pn_b    = (const float*)d_in[7];
    const float* out_w   = (const float*)d_in[8];
    const float* out_b   = (const float*)d_in[9];
    float* out = (float*)d_out;

    // 1) QKV projections -> scratch in [n,h,len,d]
    dim3 gproj(ROWS / 128, EMB / 64, 3);
    gemm_kernel<0><<<gproj, 256>>>(query, key_in, value, in_w, in_b, nullptr);

    // 2) LayerNorm K and V over D (2 * NB*NH*SK rows, 8 warps/block)
    const int ln_rows = 2 * NB * NH * SK;
    ln_kernel<<<ln_rows / 8, 256>>>(pn_w, pn_b);

    // 3) Flash attention
    dim3 gattn(LQ / 128, NB * NH);
    attn_kernel<<<gattn, 128>>>(scaling);

    // 4) Output projection -> d_out
    dim3 gout(ROWS / 128, EMB / 64, 1);
    gemm_kernel<1><<<gout, 256>>>(nullptr, nullptr, nullptr, out_w, out_b, out);
}

// round 2
// speedup vs baseline: 2.0840x; 2.0840x over previous
#include <cuda_runtime.h>

#define LQ  2048
#define SK  2048
#define NB  4
#define EMB 512
#define NH  16
#define HD  32
#define ROWS (LQ * NB)   // 8192

// Scratch (allocation-free rule: __device__ globals)
__device__ float g_Q[NB * NH * LQ * HD];   // [n,h,l,d] fp32, beta applied at attn load
__device__ float g_K[NB * NH * SK * HD];   // [n,h,s,d] (tf32-rounded after LN pass? no: fp32; cvt at attn load)
__device__ float g_V[NB * NH * SK * HD];
__device__ float g_O[ROWS * EMB];          // attention output, (l*NB+n, e) row-major

// ---------------------------------------------------------------------------
// Packed fp32x2 helpers (sm_100+): double-rate fp32 FMA, PTX-only.
// ---------------------------------------------------------------------------
__device__ __forceinline__ unsigned long long pk2(float x, float y) {
    unsigned long long r;
    asm("mov.b64 %0, {%1,%2};" : "=l"(r) : "f"(x), "f"(y));
    return r;
}
__device__ __forceinline__ unsigned long long fma2(unsigned long long a,
                                                   unsigned long long b,
                                                   unsigned long long c) {
    unsigned long long d;
    asm("fma.rn.f32x2 %0, %1, %2, %3;" : "=l"(d) : "l"(a), "l"(b), "l"(c));
    return d;
}
__device__ __forceinline__ float2 upk2(unsigned long long v) {
    float2 f;
    asm("mov.b64 {%0,%1}, %2;" : "=f"(f.x), "=f"(f.y) : "l"(v));
    return f;
}

// tf32 conversion + warp MMA
__device__ __forceinline__ unsigned f2tf(float x) {
    unsigned r;
    asm("cvt.rna.tf32.f32 %0, %1;" : "=r"(r) : "f"(x));
    return r;
}
__device__ __forceinline__ void mma_tf32(float* c, const unsigned* a,
                                         unsigned b0, unsigned b1) {
    asm volatile(
        "mma.sync.aligned.m16n8k8.row.col.f32.tf32.tf32.f32 "
        "{%0,%1,%2,%3}, {%4,%5,%6,%7}, {%8,%9}, {%0,%1,%2,%3};"
        : "+f"(c[0]), "+f"(c[1]), "+f"(c[2]), "+f"(c[3])
        : "r"(a[0]), "r"(a[1]), "r"(a[2]), "r"(a[3]), "r"(b0), "r"(b1));
}

// ---------------------------------------------------------------------------
// Tiled fp32 GEMM with packed f32x2 FMA: out[r,f] = sum_e A[r,e]*W[f,e] + b[f]
// BM=128, BN=64, BK=16, 256 threads, 8x4 microtile (paired along M).
// MODE 0: QKV projection (z picks input/weight-slice/dest, scatter epilogue)
// MODE 1: out-projection (A = g_O, row-major output)
// ---------------------------------------------------------------------------
template<int MODE>
__global__ __launch_bounds__(256)
void gemm_kernel(const float* __restrict__ Aq, const float* __restrict__ Ak,
                 const float* __restrict__ Av, const float* __restrict__ Wfull,
                 const float* __restrict__ bfull, float* __restrict__ outp)
{
    __shared__ float As[16][132];  // [k][m], padded
    __shared__ float Bs[16][68];   // [k][n]

    const int tid = threadIdx.x;
    const int r0  = blockIdx.x * 128;
    const int f0  = blockIdx.y * 64;

    const float* A;
    const float* W;
    const float* bias;
    if (MODE == 0) {
        const int z = blockIdx.z;
        A    = (z == 0) ? Aq : (z == 1) ? Ak : Av;
        W    = Wfull + z * EMB * EMB;
        bias = bfull + z * EMB;
    } else {
        A    = g_O;
        W    = Wfull;
        bias = bfull;
    }

    const int ty = tid >> 4;   // 0..15 (row group of 8)
    const int tx = tid & 15;   // 0..15 (col group of 4)

    unsigned long long acc[4][4];   // rows paired: acc[i][j] = rows (2i,2i+1), col j
    #pragma unroll
    for (int i = 0; i < 4; i++)
        #pragma unroll
        for (int j = 0; j < 4; j++) acc[i][j] = pk2(0.f, 0.f);

    for (int k0 = 0; k0 < EMB; k0 += 16) {
        #pragma unroll
        for (int t = tid; t < 512; t += 256) {
            const int row = t >> 2;
            const int kk  = (t & 3) << 2;
            const float4 v = *(const float4*)(A + (size_t)(r0 + row) * EMB + k0 + kk);
            As[kk + 0][row] = v.x;
            As[kk + 1][row] = v.y;
            As[kk + 2][row] = v.z;
            As[kk + 3][row] = v.w;
        }
        {
            const int n  = tid >> 2;
            const int kk = (tid & 3) << 2;
            const float4 v = *(const float4*)(W + (size_t)(f0 + n) * EMB + k0 + kk);
            Bs[kk + 0][n] = v.x;
            Bs[kk + 1][n] = v.y;
            Bs[kk + 2][n] = v.z;
            Bs[kk + 3][n] = v.w;
        }
        __syncthreads();

        #pragma unroll
        for (int k = 0; k < 16; k++) {
            unsigned long long a2[4];
            #pragma unroll
            for (int i = 0; i < 4; i++) {
                const float2 av = *(const float2*)&As[k][ty * 8 + 2 * i];
                a2[i] = pk2(av.x, av.y);
            }
            #pragma unroll
            for (int j = 0; j < 4; j++) {
                const float bv = Bs[k][tx * 4 + j];
                const unsigned long long b2 = pk2(bv, bv);
                #pragma unroll
                for (int i = 0; i < 4; i++)
                    acc[i][j] = fma2(a2[i], b2, acc[i][j]);
            }
        }
        __syncthreads();
    }

    if (MODE == 0) {
        float* dst = (blockIdx.z == 0) ? g_Q : (blockIdx.z == 1) ? g_K : g_V;
        #pragma unroll
        for (int i = 0; i < 4; i++) {
            #pragma unroll
            for (int j = 0; j < 4; j++) {
                const float2 v = upk2(acc[i][j]);
                const int f = f0 + tx * 4 + j;
                const int h = f >> 5;
                const int d = f & 31;
                const float bb = bias[f];
                {
                    const int r = r0 + ty * 8 + 2 * i;
                    const int l = r >> 2, n = r & 3;
                    dst[((size_t)(n * NH + h) * LQ + l) * HD + d] = v.x + bb;
                }
                {
                    const int r = r0 + ty * 8 + 2 * i + 1;
                    const int l = r >> 2, n = r & 3;
                    dst[((size_t)(n * NH + h) * LQ + l) * HD + d] = v.y + bb;
                }
            }
        }
    } else {
        #pragma unroll
        for (int i = 0; i < 4; i++) {
            #pragma unroll
            for (int j = 0; j < 4; j++) {
                const float2 v = upk2(acc[i][j]);
                const int f = f0 + tx * 4 + j;
                const float bb = bias[f];
                const int r = r0 + ty * 8 + 2 * i;
                outp[(size_t)r * EMB + f]       = v.x + bb;
                outp[(size_t)(r + 1) * EMB + f] = v.y + bb;
            }
        }
    }
}

// ---------------------------------------------------------------------------
// LayerNorm over D=32 for K and V (one warp per row)
// ---------------------------------------------------------------------------
__global__ __launch_bounds__(256)
void ln_kernel(const float* __restrict__ w, const float* __restrict__ b)
{
    const int gw   = (blockIdx.x * blockDim.x + threadIdx.x) >> 5;
    const int lane = threadIdx.x & 31;
    const int R    = NB * NH * SK;
    if (gw >= 2 * R) return;
    float* X      = (gw < R) ? g_K : g_V;
    const int row = (gw < R) ? gw : gw - R;

    float x = X[(size_t)row * HD + lane];
    float s = x;
    #pragma unroll
    for (int o = 16; o; o >>= 1) s += __shfl_xor_sync(0xffffffffu, s, o);
    const float mu = s * (1.0f / HD);
    const float dv = x - mu;
    float vv = dv * dv;
    #pragma unroll
    for (int o = 16; o; o >>= 1) vv += __shfl_xor_sync(0xffffffffu, vv, o);
    const float inv = rsqrtf(vv * (1.0f / HD) + 1e-5f);
    X[(size_t)row * HD + lane] = dv * inv * w[lane] + b[lane];
}

// ---------------------------------------------------------------------------
// Flash attention with tf32 mma.sync. Block = 128 thr (4 warps), each warp
// owns 16 query rows; block = 64 q rows of one (n,h). S chunks of 64 in smem.
// ---------------------------------------------------------------------------
__global__ __launch_bounds__(128)
void attn_mma_kernel(const float* __restrict__ scaling)
{
    __shared__ float Ks[64][36];   // tf32-rounded values, padded rows
    __shared__ float Vs[64][36];

    const int tid  = threadIdx.x;
    const int warp = tid >> 5;
    const int lane = tid & 31;
    const int g    = lane >> 2;    // row group 0..7
    const int t    = lane & 3;     // thread-in-group
    const int nh   = blockIdx.y;   // n*NH + h
    const int h    = nh & (NH - 1);
    const float beta = scaling[h];
    const int q0   = blockIdx.x * 64 + warp * 16;

    // Load Q A-fragments (4 k-steps over D=32), scale by beta, cvt tf32
    const float* Qp = g_Q + ((size_t)nh * LQ + q0) * HD;
    unsigned aq[4][4];
    #pragma unroll
    for (int ks = 0; ks < 4; ks++) {
        aq[ks][0] = f2tf(Qp[(size_t)g       * HD + ks * 8 + t]     * beta);
        aq[ks][1] = f2tf(Qp[(size_t)(g + 8) * HD + ks * 8 + t]     * beta);
        aq[ks][2] = f2tf(Qp[(size_t)g       * HD + ks * 8 + t + 4] * beta);
        aq[ks][3] = f2tf(Qp[(size_t)(g + 8) * HD + ks * 8 + t + 4] * beta);
    }

    float m0 = -1e30f, m1 = -1e30f, l0 = 0.f, l1 = 0.f;
    float o[4][4];
    #pragma unroll
    for (int nd = 0; nd < 4; nd++)
        #pragma unroll
        for (int j = 0; j < 4; j++) o[nd][j] = 0.f;

    const float* Kb = g_K + (size_t)nh * SK * HD;
    const float* Vb = g_V + (size_t)nh * SK * HD;

    for (int s0 = 0; s0 < SK; s0 += 64) {
        // Cooperative load of 64x32 K and V chunks (tf32-rounded into smem)
        #pragma unroll
        for (int i = tid; i < 512; i += 128) {
            const int row = i >> 3;
            const int dc  = (i & 7) << 2;
            float4 kv = *(const float4*)(Kb + (size_t)(s0 + row) * HD + dc);
            kv.x = __uint_as_float(f2tf(kv.x));
            kv.y = __uint_as_float(f2tf(kv.y));
            kv.z = __uint_as_float(f2tf(kv.z));
            kv.w = __uint_as_float(f2tf(kv.w));
            *(float4*)&Ks[row][dc] = kv;
            float4 vv = *(const float4*)(Vb + (size_t)(s0 + row) * HD + dc);
            vv.x = __uint_as_float(f2tf(vv.x));
            vv.y = __uint_as_float(f2tf(vv.y));
            vv.z = __uint_as_float(f2tf(vv.z));
            vv.w = __uint_as_float(f2tf(vv.w));
            *(float4*)&Vs[row][dc] = vv;
        }
        __syncthreads();

        // Scores: 8 n-tiles of 16x8, k = D in 4 steps
        float sc[8][4];
        #pragma unroll
        for (int nd = 0; nd < 8; nd++) {
            sc[nd][0] = sc[nd][1] = sc[nd][2] = sc[nd][3] = 0.f;
            #pragma unroll
            for (int ks = 0; ks < 4; ks++) {
                const unsigned b0 = __float_as_uint(Ks[nd * 8 + g][ks * 8 + t]);
                const unsigned b1 = __float_as_uint(Ks[nd * 8 + g][ks * 8 + t + 4]);
                mma_tf32(sc[nd], aq[ks], b0, b1);
            }
        }

        // Online softmax (rows g: sc[.][0,1]; rows g+8: sc[.][2,3])
        float t0 = -1e30f, t1 = -1e30f;
        #pragma unroll
        for (int nd = 0; nd < 8; nd++) {
            t0 = fmaxf(t0, fmaxf(sc[nd][0], sc[nd][1]));
            t1 = fmaxf(t1, fmaxf(sc[nd][2], sc[nd][3]));
        }
        t0 = fmaxf(t0, __shfl_xor_sync(0xffffffffu, t0, 1));
        t0 = fmaxf(t0, __shfl_xor_sync(0xffffffffu, t0, 2));
        t1 = fmaxf(t1, __shfl_xor_sync(0xffffffffu, t1, 1));
        t1 = fmaxf(t1, __shfl_xor_sync(0xffffffffu, t1, 2));

        const float nm0 = fmaxf(m0, t0);
        const float nm1 = fmaxf(m1, t1);
        const float c0  = __expf(m0 - nm0);
        const float c1  = __expf(m1 - nm1);

        float rs0 = 0.f, rs1 = 0.f;
        #pragma unroll
        for (int nd = 0; nd < 8; nd++) {
            sc[nd][0] = __expf(sc[nd][0] - nm0);
            sc[nd][1] = __expf(sc[nd][1] - nm0);
            sc[nd][2] = __expf(sc[nd][2] - nm1);
            sc[nd][3] = __expf(sc[nd][3] - nm1);
            rs0 += sc[nd][0] + sc[nd][1];
            rs1 += sc[nd][2] + sc[nd][3];
        }
        rs0 += __shfl_xor_sync(0xffffffffu, rs0, 1);
        rs0 += __shfl_xor_sync(0xffffffffu, rs0, 2);
        rs1 += __shfl_xor_sync(0xffffffffu, rs1, 1);
        rs1 += __shfl_xor_sync(0xffffffffu, rs1, 2);

        l0 = l0 * c0 + rs0;
        l1 = l1 * c1 + rs1;
        #pragma unroll
        for (int nd = 0; nd < 4; nd++) {
            o[nd][0] *= c0; o[nd][1] *= c0;
            o[nd][2] *= c1; o[nd][3] *= c1;
        }
        m0 = nm0; m1 = nm1;

        // PV: 8 k-steps over s, 4 n-tiles over d. Convert P C-frag -> A-frag
        // via intra-quad shuffles: A(g,t), A(g+8,t), A(g,t+4), A(g+8,t+4).
        const int sA = t >> 1;
        const int sB = sA + 2;
        const bool odd = (t & 1);
        #pragma unroll
        for (int kst = 0; kst < 8; kst++) {
            const float p0 = sc[kst][0], p1 = sc[kst][1];
            const float p2 = sc[kst][2], p3 = sc[kst][3];
            const float x0 = __shfl_sync(0xffffffffu, p0, sA, 4);
            const float x1 = __shfl_sync(0xffffffffu, p1, sA, 4);
            const float y0 = __shfl_sync(0xffffffffu, p0, sB, 4);
            const float y1 = __shfl_sync(0xffffffffu, p1, sB, 4);
            const float z0 = __shfl_sync(0xffffffffu, p2, sA, 4);
            const float z1 = __shfl_sync(0xffffffffu, p3, sA, 4);
            const float w0 = __shfl_sync(0xffffffffu, p2, sB, 4);
            const float w1 = __shfl_sync(0xffffffffu, p3, sB, 4);
            unsigned ap[4];
            ap[0] = f2tf(odd ? x1 : x0);
            ap[1] = f2tf(odd ? z1 : z0);
            ap[2] = f2tf(odd ? y1 : y0);
            ap[3] = f2tf(odd ? w1 : w0);
            #pragma unroll
            for (int nd = 0; nd < 4; nd++) {
                const unsigned b0 = __float_as_uint(Vs[kst * 8 + t][nd * 8 + g]);
                const unsigned b1 = __float_as_uint(Vs[kst * 8 + t + 4][nd * 8 + g]);
                mma_tf32(o[nd], ap, b0, b1);
            }
        }
        __syncthreads();
    }

    // Epilogue: divide by l, scatter to g_O[(l*NB+n)*EMB + h*32 + d]
    const float i0 = 1.0f / l0;
    const float i1 = 1.0f / l1;
    const int n = nh >> 4;
    float* op0 = g_O + ((size_t)(q0 + g)     * NB + n) * EMB + h * HD;
    float* op1 = g_O + ((size_t)(q0 + g + 8) * NB + n) * EMB + h * HD;
    #pragma unroll
    for (int nd = 0; nd < 4; nd++) {
        const int col = nd * 8 + 2 * t;
        float2 v0 = make_float2(o[nd][0] * i0, o[nd][1] * i0);
        float2 v1 = make_float2(o[nd][2] * i1, o[nd][3] * i1);
        *(float2*)(op0 + col) = v0;
        *(float2*)(op1 + col) = v1;
    }
}

// ---------------------------------------------------------------------------
extern "C" void kernel_launch(void* const* d_in, const int* in_sizes, int n_in,
                              void* d_out, int out_size)
{
    const float* query   = (const float*)d_in[0];
    const float* key_in  = (const float*)d_in[1];
    const float* value   = (const float*)d_in[2];
    const float* scaling = (const float*)d_in[3];
    const float* in_w    = (const float*)d_in[4];
    const float* in_b    = (const float*)d_in[5];
    const float* pn_w    = (const float*)d_in[6];
    const float* pn_b    = (const float*)d_in[7];
    const float* out_w   = (const float*)d_in[8];
    const float* out_b   = (const float*)d_in[9];
    float* out = (float*)d_out;

    // 1) QKV projections -> scratch in [n,h,len,d]
    dim3 gproj(ROWS / 128, EMB / 64, 3);
    gemm_kernel<0><<<gproj, 256>>>(query, key_in, value, in_w, in_b, nullptr);

    // 2) LayerNorm K and V over D
    const int ln_rows = 2 * NB * NH * SK;
    ln_kernel<<<ln_rows / 8, 256>>>(pn_w, pn_b);

    // 3) Flash attention (tf32 tensor-core)
    dim3 gattn(LQ / 64, NB * NH);
    attn_mma_kernel<<<gattn, 128>>>(scaling);

    // 4) Output projection -> d_out
    dim3 gout(ROWS / 128, EMB / 64, 1);
    gemm_kernel<1><<<gout, 256>>>(nullptr, nullptr, nullptr, out_w, out_b, out);
}

// round 3
// speedup vs baseline: 2.0855x; 1.0007x over previous
#include <cuda_runtime.h>

#define LQ  2048
#define SK  2048
#define NB  4
#define EMB 512
#define NH  16
#define HD  32
#define ROWS (LQ * NB)   // 8192

// Scratch (allocation-free rule: __device__ globals)
__device__ float g_Q[NB * NH * LQ * HD];   // [n,h,l,d] fp32, beta applied at attn load
__device__ float g_K[NB * NH * SK * HD];   // [n,h,s,d] (tf32-rounded after LN pass? no: fp32; cvt at attn load)
__device__ float g_V[NB * NH * SK * HD];
__device__ float g_O[ROWS * EMB];          // attention output, (l*NB+n, e) row-major

// ---------------------------------------------------------------------------
// Packed fp32x2 helpers (sm_100+): double-rate fp32 FMA, PTX-only.
// ---------------------------------------------------------------------------
__device__ __forceinline__ unsigned long long pk2(float x, float y) {
    unsigned long long r;
    asm("mov.b64 %0, {%1,%2};" : "=l"(r) : "f"(x), "f"(y));
    return r;
}
__device__ __forceinline__ unsigned long long fma2(unsigned long long a,
                                                   unsigned long long b,
                                                   unsigned long long c) {
    unsigned long long d;
    asm("fma.rn.f32x2 %0, %1, %2, %3;" : "=l"(d) : "l"(a), "l"(b), "l"(c));
    return d;
}
__device__ __forceinline__ float2 upk2(unsigned long long v) {
    float2 f;
    asm("mov.b64 {%0,%1}, %2;" : "=f"(f.x), "=f"(f.y) : "l"(v));
    return f;
}

// tf32 conversion + warp MMA
__device__ __forceinline__ unsigned f2tf(float x) {
    unsigned r;
    asm("cvt.rna.tf32.f32 %0, %1;" : "=r"(r) : "f"(x));
    return r;
}
__device__ __forceinline__ void mma_tf32(float* c, const unsigned* a,
                                         unsigned b0, unsigned b1) {
    asm volatile(
        "mma.sync.aligned.m16n8k8.row.col.f32.tf32.tf32.f32 "
        "{%0,%1,%2,%3}, {%4,%5,%6,%7}, {%8,%9}, {%0,%1,%2,%3};"
        : "+f"(c[0]), "+f"(c[1]), "+f"(c[2]), "+f"(c[3])
        : "r"(a[0]), "r"(a[1]), "r"(a[2]), "r"(a[3]), "r"(b0), "r"(b1));
}

// ---------------------------------------------------------------------------
// Tiled fp32 GEMM with packed f32x2 FMA: out[r,f] = sum_e A[r,e]*W[f,e] + b[f]
// BM=128, BN=64, BK=16, 256 threads, 8x4 microtile (paired along M).
// MODE 0: QKV projection (z picks input/weight-slice/dest, scatter epilogue)
// MODE 1: out-projection (A = g_O, row-major output)
// ---------------------------------------------------------------------------
template<int MODE>
__global__ __launch_bounds__(256)
void gemm_kernel(const float* __restrict__ Aq, const float* __restrict__ Ak,
                 const float* __restrict__ Av, const float* __restrict__ Wfull,
                 const float* __restrict__ bfull, float* __restrict__ outp)
{
    __shared__ float As[16][132];  // [k][m], padded
    __shared__ float Bs[16][68];   // [k][n]

    const int tid = threadIdx.x;
    const int r0  = blockIdx.x * 128;
    const int f0  = blockIdx.y * 64;

    const float* A;
    const float* W;
    const float* bias;
    if (MODE == 0) {
        const int z = blockIdx.z;
        A    = (z == 0) ? Aq : (z == 1) ? Ak : Av;
        W    = Wfull + z * EMB * EMB;
        bias = bfull + z * EMB;
    } else {
        A    = g_O;
        W    = Wfull;
        bias = bfull;
    }

    const int ty = tid >> 4;   // 0..15 (row group of 8)
    const int tx = tid & 15;   // 0..15 (col group of 4)

    unsigned long long acc[4][4];   // rows paired: acc[i][j] = rows (2i,2i+1), col j
    #pragma unroll
    for (int i = 0; i < 4; i++)
        #pragma unroll
        for (int j = 0; j < 4; j++) acc[i][j] = pk2(0.f, 0.f);

    for (int k0 = 0; k0 < EMB; k0 += 16) {
        #pragma unroll
        for (int t = tid; t < 512; t += 256) {
            const int row = t >> 2;
            const int kk  = (t & 3) << 2;
            const float4 v = *(const float4*)(A + (size_t)(r0 + row) * EMB + k0 + kk);
            As[kk + 0][row] = v.x;
            As[kk + 1][row] = v.y;
            As[kk + 2][row] = v.z;
            As[kk + 3][row] = v.w;
        }
        {
            const int n  = tid >> 2;
            const int kk = (tid & 3) << 2;
            const float4 v = *(const float4*)(W + (size_t)(f0 + n) * EMB + k0 + kk);
            Bs[kk + 0][n] = v.x;
            Bs[kk + 1][n] = v.y;
            Bs[kk + 2][n] = v.z;
            Bs[kk + 3][n] = v.w;
        }
        __syncthreads();

        #pragma unroll
        for (int k = 0; k < 16; k++) {
            unsigned long long a2[4];
            #pragma unroll
            for (int i = 0; i < 4; i++) {
                const float2 av = *(const float2*)&As[k][ty * 8 + 2 * i];
                a2[i] = pk2(av.x, av.y);
            }
            #pragma unroll
            for (int j = 0; j < 4; j++) {
                const float bv = Bs[k][tx * 4 + j];
                const unsigned long long b2 = pk2(bv, bv);
                #pragma unroll
                for (int i = 0; i < 4; i++)
                    acc[i][j] = fma2(a2[i], b2, acc[i][j]);
            }
        }
        __syncthreads();
    }

    if (MODE == 0) {
        float* dst = (blockIdx.z == 0) ? g_Q : (blockIdx.z == 1) ? g_K : g_V;
        #pragma unroll
        for (int i = 0; i < 4; i++) {
            #pragma unroll
            for (int j = 0; j < 4; j++) {
                const float2 v = upk2(acc[i][j]);
                const int f = f0 + tx * 4 + j;
                const int h = f >> 5;
                const int d = f & 31;
                const float bb = bias[f];
                {
                    const int r = r0 + ty * 8 + 2 * i;
                    const int l = r >> 2, n = r & 3;
                    dst[((size_t)(n * NH + h) * LQ + l) * HD + d] = v.x + bb;
                }
                {
                    const int r = r0 + ty * 8 + 2 * i + 1;
                    const int l = r >> 2, n = r & 3;
                    dst[((size_t)(n * NH + h) * LQ + l) * HD + d] = v.y + bb;
                }
            }
        }
    } else {
        #pragma unroll
        for (int i = 0; i < 4; i++) {
            #pragma unroll
            for (int j = 0; j < 4; j++) {
                const float2 v = upk2(acc[i][j]);
                const int f = f0 + tx * 4 + j;
                const float bb = bias[f];
                const int r = r0 + ty * 8 + 2 * i;
                outp[(size_t)r * EMB + f]       = v.x + bb;
                outp[(size_t)(r + 1) * EMB + f] = v.y + bb;
            }
        }
    }
}

// ---------------------------------------------------------------------------
// LayerNorm over D=32 for K and V (one warp per row)
// ---------------------------------------------------------------------------
__global__ __launch_bounds__(256)
void ln_kernel(const float* __restrict__ w, const float* __restrict__ b)
{
    const int gw   = (blockIdx.x * blockDim.x + threadIdx.x) >> 5;
    const int lane = threadIdx.x & 31;
    const int R    = NB * NH * SK;
    if (gw >= 2 * R) return;
    float* X      = (gw < R) ? g_K : g_V;
    const int row = (gw < R) ? gw : gw - R;

    float x = X[(size_t)row * HD + lane];
    float s = x;
    #pragma unroll
    for (int o = 16; o; o >>= 1) s += __shfl_xor_sync(0xffffffffu, s, o);
    const float mu = s * (1.0f / HD);
    const float dv = x - mu;
    float vv = dv * dv;
    #pragma unroll
    for (int o = 16; o; o >>= 1) vv += __shfl_xor_sync(0xffffffffu, vv, o);
    const float inv = rsqrtf(vv * (1.0f / HD) + 1e-5f);
    X[(size_t)row * HD + lane] = dv * inv * w[lane] + b[lane];
}

// ---------------------------------------------------------------------------
// Flash attention with tf32 mma.sync. Block = 128 thr (4 warps), each warp
// owns 16 query rows; block = 64 q rows of one (n,h). S chunks of 64 in smem.
// ---------------------------------------------------------------------------
__global__ __launch_bounds__(128)
void attn_mma_kernel(const float* __restrict__ scaling)
{
    __shared__ float Ks[64][36];   // tf32-rounded values, padded rows
    __shared__ float Vs[64][36];

    const int tid  = threadIdx.x;
    const int warp = tid >> 5;
    const int lane = tid & 31;
    const int g    = lane >> 2;    // row group 0..7
    const int t    = lane & 3;     // thread-in-group
    const int nh   = blockIdx.y;   // n*NH + h
    const int h    = nh & (NH - 1);
    const float beta = scaling[h];
    const int q0   = blockIdx.x * 64 + warp * 16;

    // Load Q A-fragments (4 k-steps over D=32), scale by beta, cvt tf32
    const float* Qp = g_Q + ((size_t)nh * LQ + q0) * HD;
    unsigned aq[4][4];
    #pragma unroll
    for (int ks = 0; ks < 4; ks++) {
        aq[ks][0] = f2tf(Qp[(size_t)g       * HD + ks * 8 + t]     * beta);
        aq[ks][1] = f2tf(Qp[(size_t)(g + 8) * HD + ks * 8 + t]     * beta);
        aq[ks][2] = f2tf(Qp[(size_t)g       * HD + ks * 8 + t + 4] * beta);
        aq[ks][3] = f2tf(Qp[(size_t)(g + 8) * HD + ks * 8 + t + 4] * beta);
    }

    float m0 = -1e30f, m1 = -1e30f, l0 = 0.f, l1 = 0.f;
    float o[4][4];
    #pragma unroll
    for (int nd = 0; nd < 4; nd++)
        #pragma unroll
        for (int j = 0; j < 4; j++) o[nd][j] = 0.f;

    const float* Kb = g_K + (size_t)nh * SK * HD;
    const float* Vb = g_V + (size_t)nh * SK * HD;

    for (int s0 = 0; s0 < SK; s0 += 64) {
        // Cooperative load of 64x32 K and V chunks (tf32-rounded into smem)
        #pragma unroll
        for (int i = tid; i < 512; i += 128) {
            const int row = i >> 3;
            const int dc  = (i & 7) << 2;
            float4 kv = *(const float4*)(Kb + (size_t)(s0 + row) * HD + dc);
            kv.x = __uint_as_float(f2tf(kv.x));
            kv.y = __uint_as_float(f2tf(kv.y));
            kv.z = __uint_as_float(f2tf(kv.z));
            kv.w = __uint_as_float(f2tf(kv.w));
            *(float4*)&Ks[row][dc] = kv;
            float4 vv = *(const float4*)(Vb + (size_t)(s0 + row) * HD + dc);
            vv.x = __uint_as_float(f2tf(vv.x));
            vv.y = __uint_as_float(f2tf(vv.y));
            vv.z = __uint_as_float(f2tf(vv.z));
            vv.w = __uint_as_float(f2tf(vv.w));
            *(float4*)&Vs[row][dc] = vv;
        }
        __syncthreads();

        // Scores: 8 n-tiles of 16x8, k = D in 4 steps
        float sc[8][4];
        #pragma unroll
        for (int nd = 0; nd < 8; nd++) {
            sc[nd][0] = sc[nd][1] = sc[nd][2] = sc[nd][3] = 0.f;
            #pragma unroll
            for (int ks = 0; ks < 4; ks++) {
                const unsigned b0 = __float_as_uint(Ks[nd * 8 + g][ks * 8 + t]);
                const unsigned b1 = __float_as_uint(Ks[nd * 8 + g][ks * 8 + t + 4]);
                mma_tf32(sc[nd], aq[ks], b0, b1);
            }
        }

        // Online softmax (rows g: sc[.][0,1]; rows g+8: sc[.][2,3])
        float t0 = -1e30f, t1 = -1e30f;
        #pragma unroll
        for (int nd = 0; nd < 8; nd++) {
            t0 = fmaxf(t0, fmaxf(sc[nd][0], sc[nd][1]));
            t1 = fmaxf(t1, fmaxf(sc[nd][2], sc[nd][3]));
        }
        t0 = fmaxf(t0, __shfl_xor_sync(0xffffffffu, t0, 1));
        t0 = fmaxf(t0, __shfl_xor_sync(0xffffffffu, t0, 2));
        t1 = fmaxf(t1, __shfl_xor_sync(0xffffffffu, t1, 1));
        t1 = fmaxf(t1, __shfl_xor_sync(0xffffffffu, t1, 2));

        const float nm0 = fmaxf(m0, t0);
        const float nm1 = fmaxf(m1, t1);
        const float c0  = __expf(m0 - nm0);
        const float c1  = __expf(m1 - nm1);

        float rs0 = 0.f, rs1 = 0.f;
        #pragma unroll
        for (int nd = 0; nd < 8; nd++) {
            sc[nd][0] = __expf(sc[nd][0] - nm0);
            sc[nd][1] = __expf(sc[nd][1] - nm0);
            sc[nd][2] = __expf(sc[nd][2] - nm1);
            sc[nd][3] = __expf(sc[nd][3] - nm1);
            rs0 += sc[nd][0] + sc[nd][1];
            rs1 += sc[nd][2] + sc[nd][3];
        }
        rs0 += __shfl_xor_sync(0xffffffffu, rs0, 1);
        rs0 += __shfl_xor_sync(0xffffffffu, rs0, 2);
        rs1 += __shfl_xor_sync(0xffffffffu, rs1, 1);
        rs1 += __shfl_xor_sync(0xffffffffu, rs1, 2);

        l0 = l0 * c0 + rs0;
        l1 = l1 * c1 + rs1;
        #pragma unroll
        for (int nd = 0; nd < 4; nd++) {
            o[nd][0] *= c0; o[nd][1] *= c0;
            o[nd][2] *= c1; o[nd][3] *= c1;
        }
        m0 = nm0; m1 = nm1;

        // PV: 8 k-steps over s, 4 n-tiles over d. Convert P C-frag -> A-frag
        // via intra-quad shuffles: A(g,t), A(g+8,t), A(g,t+4), A(g+8,t+4).
        const int sA = t >> 1;
        const int sB = sA + 2;
        const bool odd = (t & 1);
        #pragma unroll
        for (int kst = 0; kst < 8; kst++) {
            const float p0 = sc[kst][0], p1 = sc[kst][1];
            const float p2 = sc[kst][2], p3 = sc[kst][3];
            const float x0 = __shfl_sync(0xffffffffu, p0, sA, 4);
            const float x1 = __shfl_sync(0xffffffffu, p1, sA, 4);
            const float y0 = __shfl_sync(0xffffffffu, p0, sB, 4);
            const float y1 = __shfl_sync(0xffffffffu, p1, sB, 4);
            const float z0 = __shfl_sync(0xffffffffu, p2, sA, 4);
            const float z1 = __shfl_sync(0xffffffffu, p3, sA, 4);
            const float w0 = __shfl_sync(0xffffffffu, p2, sB, 4);
            const float w1 = __shfl_sync(0xffffffffu, p3, sB, 4);
            unsigned ap[4];
            ap[0] = f2tf(odd ? x1 : x0);
            ap[1] = f2tf(odd ? z1 : z0);
            ap[2] = f2tf(odd ? y1 : y0);
            ap[3] = f2tf(odd ? w1 : w0);
            #pragma unroll
            for (int nd = 0; nd < 4; nd++) {
                const unsigned b0 = __float_as_uint(Vs[kst * 8 + t][nd * 8 + g]);
                const unsigned b1 = __float_as_uint(Vs[kst * 8 + t + 4][nd * 8 + g]);
                mma_tf32(o[nd], ap, b0, b1);
            }
        }
        __syncthreads();
    }

    // Epilogue: divide by l, scatter to g_O[(l*NB+n)*EMB + h*32 + d]
    const float i0 = 1.0f / l0;
    const float i1 = 1.0f / l1;
    const int n = nh >> 4;
    float* op0 = g_O + ((size_t)(q0 + g)     * NB + n) * EMB + h * HD;
    float* op1 = g_O + ((size_t)(q0 + g + 8) * NB + n) * EMB + h * HD;
    #pragma unroll
    for (int nd = 0; nd < 4; nd++) {
        const int col = nd * 8 + 2 * t;
        float2 v0 = make_float2(o[nd][0] * i0, o[nd][1] * i0);
        float2 v1 = make_float2(o[nd][2] * i1, o[nd][3] * i1);
        *(float2*)(op0 + col) = v0;
        *(float2*)(op1 + col) = v1;
    }
}

// ---------------------------------------------------------------------------
extern "C" void kernel_launch(void* const* d_in, const int* in_sizes, int n_in,
                              void* d_out, int out_size)
{
    const float* query   = (const float*)d_in[0];
    const float* key_in  = (const float*)d_in[1];
    const float* value   = (const float*)d_in[2];
    const float* scaling = (const float*)d_in[3];
    const float* in_w    = (const float*)d_in[4];
    const float* in_b    = (const float*)d_in[5];
    const float* pn_w    = (const float*)d_in[6];
    const float* pn_b    = (const float*)d_in[7];
    const float* out_w   = (const float*)d_in[8];
    const float* out_b   = (const float*)d_in[9];
    float* out = (float*)d_out;

    // 1) QKV projections -> scratch in [n,h,len,d]
    dim3 gproj(ROWS / 128, EMB / 64, 3);
    gemm_kernel<0><<<gproj, 256>>>(query, key_in, value, in_w, in_b, nullptr);

    // 2) LayerNorm K and V over D
    const int ln_rows = 2 * NB * NH * SK;
    ln_kernel<<<ln_rows / 8, 256>>>(pn_w, pn_b);

    // 3) Flash attention (tf32 tensor-core)
    dim3 gattn(LQ / 64, NB * NH);
    attn_mma_kernel<<<gattn, 128>>>(scaling);

    // 4) Output projection -> d_out
    dim3 gout(ROWS / 128, EMB / 64, 1);
    gemm_kernel<1><<<gout, 256>>>(nullptr, nullptr, nullptr, out_w, out_b, out);
}